// round 3
// baseline (speedup 1.0000x reference)
#include <cuda_runtime.h>
#include <stdint.h>

// FloodPath: 16-step binary flood fill on a 4096x4096 grid.
// Bit-packed cellular automaton, fully fused in one kernel:
//   pack (ballot) -> 16 smem bitwise steps (32-halo tiles) -> unpack.
// Count accumulated via 5 register bit-planes (ripple-carry adder).

#define HW    4096
#define CORE  256
#define HALO  32
#define PAD   320          // CORE + 2*HALO
#define WPR   10           // PAD / 32 words per padded row
#define NWORDS (PAD * WPR) // 3200
#define NT    512
#define STEPS 16

__global__ void __launch_bounds__(NT, 2)
flood_kernel(const float2* __restrict__ in, float* __restrict__ out)
{
    __shared__ uint32_t sm_free[NWORDS]; // bit=1: free AND inside image
    __shared__ uint32_t sm_a[NWORDS];
    __shared__ uint32_t sm_b[NWORDS];

    const int tid  = threadIdx.x;
    const int lane = tid & 31;
    const int warp = tid >> 5;
    const int tile_x = (blockIdx.x & 15) * CORE;
    const int tile_y = (blockIdx.x >> 4) * CORE;

    // ---- pack: one word per warp-iteration via ballot (coalesced 256B loads)
    for (int w = warp; w < NWORDS; w += NT / 32) {
        int prow = w / WPR;
        int pcol = w - prow * WPR;
        int gy = tile_y - HALO + prow;
        int gx = tile_x - HALO + pcol * 32 + lane;
        bool inr = (gy >= 0) && (gy < HW) && (gx >= 0) && (gx < HW);
        float2 v = make_float2(0.f, 0.f);
        if (inr) v = in[(size_t)gy * HW + gx];
        // outside image behaves as occupied (SAME zero padding: never floods)
        uint32_t freeb = __ballot_sync(0xffffffffu, inr && (v.x == 0.f));
        uint32_t fldb  = __ballot_sync(0xffffffffu, v.y != 0.f);
        if (lane == 0) { sm_free[w] = freeb; sm_a[w] = fldb; }
    }
    __syncthreads();

    // per-thread 5-bit-plane counters for 4 owned core words
    uint32_t c0[4] = {0,0,0,0}, c1[4] = {0,0,0,0}, c2[4] = {0,0,0,0},
             c3[4] = {0,0,0,0}, c4[4] = {0,0,0,0};

    uint32_t* src = sm_a;
    uint32_t* dst = sm_b;

    for (int step = 0; step < STEPS; step++) {
        for (int w = tid; w < NWORDS; w += NT) {
            int prow = w / WPR;
            int pcol = w - prow * WPR;
            uint32_t s  = src[w];
            uint32_t up = (prow > 0)       ? src[w - WPR] : 0u;
            uint32_t dn = (prow < PAD - 1) ? src[w + WPR] : 0u;
            uint32_t lf = (pcol > 0)       ? src[w - 1]   : 0u;
            uint32_t rt = (pcol < WPR - 1) ? src[w + 1]   : 0u;
            uint32_t nf = s | up | dn
                        | (s << 1) | (lf >> 31)
                        | (s >> 1) | (rt << 31);
            dst[w] = nf & sm_free[w];
        }
        __syncthreads();
        // accumulate count (reads dst; next step writes the *other* plane, so
        // one barrier per step is sufficient)
#pragma unroll
        for (int i = 0; i < 4; i++) {
            int cw   = tid + i * NT;          // core word id in [0,2048)
            int crow = cw >> 3;
            int ccol = cw & 7;
            uint32_t b = dst[(crow + HALO) * WPR + (ccol + 1)];
            uint32_t carry = b, t;
            t = c0[i] & carry; c0[i] ^= carry; carry = t;
            t = c1[i] & carry; c1[i] ^= carry; carry = t;
            t = c2[i] & carry; c2[i] ^= carry; carry = t;
            t = c3[i] & carry; c3[i] ^= carry; carry = t;
            c4[i] ^= carry;
        }
        uint32_t* tmp = src; src = dst; dst = tmp;
    }
    // final flood now lives in src (fully written before last barrier)

    // ---- unpack: each thread expands its 4 core words to [occ,flood,count]
#pragma unroll
    for (int i = 0; i < 4; i++) {
        int cw   = tid + i * NT;
        int crow = cw >> 3;
        int ccol = cw & 7;
        int pidx = (crow + HALO) * WPR + (ccol + 1);
        uint32_t fw = src[pidx];
        uint32_t fr = sm_free[pidx];
        int gy  = tile_y + crow;
        int gx0 = tile_x + ccol * 32;
        float4* o4 = (float4*)(out + ((size_t)gy * HW + gx0) * 3);
#pragma unroll
        for (int j = 0; j < 24; j++) {   // 32 cells * 3 floats = 24 float4
            float4 v;
            float* e = (float*)&v;
#pragma unroll
            for (int k = 0; k < 4; k++) {
                int m  = j * 4 + k;
                int b  = m / 3;          // cell (compile-time)
                int ch = m - b * 3;      // channel (compile-time)
                float val;
                if (ch == 0) {
                    val = ((fr >> b) & 1u) ? 0.0f : 1.0f;   // occupied
                } else if (ch == 1) {
                    val = ((fw >> b) & 1u) ? 1.0f : 0.0f;   // flood
                } else {
                    uint32_t c =  ((c0[i] >> b) & 1u)
                               | (((c1[i] >> b) & 1u) << 1)
                               | (((c2[i] >> b) & 1u) << 2)
                               | (((c3[i] >> b) & 1u) << 3)
                               | (((c4[i] >> b) & 1u) << 4);
                    val = (float)c;                          // count 0..16
                }
                e[k] = val;
            }
            o4[j] = v;
        }
    }
}

extern "C" void kernel_launch(void* const* d_in, const int* in_sizes, int n_in,
                              void* d_out, int out_size)
{
    const float2* in  = (const float2*)d_in[0]; // flood_input [H,W,2] f32
    float*        out = (float*)d_out;          // [H,W,3] f32
    (void)in_sizes; (void)n_in; (void)out_size;
    flood_kernel<<<256, NT>>>(in, out);
}